// round 3
// baseline (speedup 1.0000x reference)
#include <cuda_runtime.h>

#define C_M 256
#define C_Z 128
#define NDIM 768
#define S_DIM 128
#define BIN_COUNT 15
#define BIN_START 3.25f
#define BIN_STEP 1.25f
#define LN_EPS 1e-5f

// ---------------------------------------------------------------------------
// Kernel 1: bulk copy of m -> out_m (float4 vectorized)
// ---------------------------------------------------------------------------
__global__ void copy_m_kernel(const float4* __restrict__ src,
                              float4* __restrict__ dst, int n4) {
    int i = blockIdx.x * blockDim.x + threadIdx.x;
    if (i < n4) dst[i] = src[i];
}

// ---------------------------------------------------------------------------
// Kernel 2: out_m[0,j,:] = m[0,j,:] + LayerNorm(m_prev[0,j,:])
// one warp per row, 256 channels -> 2 float4 per lane
// ---------------------------------------------------------------------------
__global__ __launch_bounds__(256) void m0_kernel(
    const float* __restrict__ m, const float* __restrict__ m_prev,
    const float* __restrict__ w, const float* __restrict__ b,
    float* __restrict__ out) {
    int gwarp = (blockIdx.x * blockDim.x + threadIdx.x) >> 5;
    int lane = threadIdx.x & 31;
    if (gwarp >= NDIM) return;

    const float4* mp4 = (const float4*)(m_prev + (size_t)gwarp * C_M);
    float4 v0 = mp4[lane * 2];
    float4 v1 = mp4[lane * 2 + 1];

    float s  = v0.x + v0.y + v0.z + v0.w + v1.x + v1.y + v1.z + v1.w;
    float ss = v0.x*v0.x + v0.y*v0.y + v0.z*v0.z + v0.w*v0.w
             + v1.x*v1.x + v1.y*v1.y + v1.z*v1.z + v1.w*v1.w;
    #pragma unroll
    for (int o = 16; o > 0; o >>= 1) {
        s  += __shfl_xor_sync(0xFFFFFFFFu, s,  o);
        ss += __shfl_xor_sync(0xFFFFFFFFu, ss, o);
    }
    const float inv = 1.0f / C_M;
    float mu = s * inv;
    float var = ss * inv - mu * mu;
    float rs = rsqrtf(var + LN_EPS);

    const float4* mm4 = (const float4*)(m + (size_t)gwarp * C_M);
    const float4* w4 = (const float4*)w;
    const float4* b4 = (const float4*)b;
    float4* o4 = (float4*)(out + (size_t)gwarp * C_M);

    #pragma unroll
    for (int h = 0; h < 2; h++) {
        float4 a = mm4[lane * 2 + h];
        float4 v = (h == 0) ? v0 : v1;
        float4 wv = w4[lane * 2 + h];
        float4 bv = b4[lane * 2 + h];
        float4 r;
        r.x = a.x + (v.x - mu) * rs * wv.x + bv.x;
        r.y = a.y + (v.y - mu) * rs * wv.y + bv.y;
        r.z = a.z + (v.z - mu) * rs * wv.z + bv.z;
        r.w = a.w + (v.w - mu) * rs * wv.w + bv.w;
        o4[lane * 2 + h] = r;
    }
}

// ---------------------------------------------------------------------------
// Kernel 3: out_z[i,j,:] = z[i,j,:] + emb(i,j) + LayerNorm(z_prev[i,j,:])
// one warp per (i,j) row, 128 channels -> 1 float4 per lane
// ---------------------------------------------------------------------------
__global__ __launch_bounds__(256) void z_kernel(
    const float* __restrict__ z, const float* __restrict__ z_prev,
    const float* __restrict__ x_prev,
    const float* __restrict__ ln_w, const float* __restrict__ ln_b,
    const float* __restrict__ lin_w, const float* __restrict__ lin_b,
    float* __restrict__ out) {
    // shared: lin_w transposed [bin][channel] for conflict-free access
    __shared__ float s_lwT[BIN_COUNT * C_Z];
    __shared__ float s_lb[C_Z];
    __shared__ float s_w[C_Z];
    __shared__ float s_b[C_Z];

    int tid = threadIdx.x;
    for (int k = tid; k < BIN_COUNT * C_Z; k += 256) {
        int bb = k / C_Z;
        int cc = k - bb * C_Z;
        s_lwT[k] = lin_w[cc * BIN_COUNT + bb];
    }
    if (tid < C_Z) {
        s_lb[tid] = lin_b[tid];
        s_w[tid]  = ln_w[tid];
        s_b[tid]  = ln_b[tid];
    }
    __syncthreads();

    int warp = tid >> 5;
    int lane = tid & 31;
    long row = (long)blockIdx.x * 8 + warp;
    if (row >= (long)NDIM * NDIM) return;

    int i = (int)(row / NDIM);
    int j = (int)(row - (long)i * NDIM);

    // pairwise distance (all lanes compute; x_prev broadcasts via L1)
    float dx = x_prev[i * 3 + 0] - x_prev[j * 3 + 0];
    float dy = x_prev[i * 3 + 1] - x_prev[j * 3 + 1];
    float dz = x_prev[i * 3 + 2] - x_prev[j * 3 + 2];
    float d = sqrtf(dx * dx + dy * dy + dz * dz);

    // bin search matching reference semantics exactly (strict bounds)
    int bin = -1;
    #pragma unroll
    for (int k = 0; k < BIN_COUNT; k++) {
        float lo = BIN_START + k * BIN_STEP;
        float hi = (k < BIN_COUNT - 1) ? (lo + BIN_STEP) : 1e8f;
        if (d > lo && d < hi) bin = k;
    }

    size_t base = (size_t)row * C_Z;
    const float4* zp4 = (const float4*)(z_prev + base);
    float4 p = zp4[lane];

    float s  = p.x + p.y + p.z + p.w;
    float ss = p.x*p.x + p.y*p.y + p.z*p.z + p.w*p.w;
    #pragma unroll
    for (int o = 16; o > 0; o >>= 1) {
        s  += __shfl_xor_sync(0xFFFFFFFFu, s,  o);
        ss += __shfl_xor_sync(0xFFFFFFFFu, ss, o);
    }
    const float inv = 1.0f / C_Z;
    float mu = s * inv;
    float var = ss * inv - mu * mu;
    float rs = rsqrtf(var + LN_EPS);

    const float4* z4 = (const float4*)(z + base);
    float4 a = z4[lane];
    int c = lane * 4;

    float e0 = s_lb[c + 0], e1 = s_lb[c + 1], e2 = s_lb[c + 2], e3 = s_lb[c + 3];
    if (bin >= 0) {
        const float* lw = s_lwT + bin * C_Z + c;
        e0 += lw[0]; e1 += lw[1]; e2 += lw[2]; e3 += lw[3];
    }

    float4 r;
    r.x = a.x + e0 + (p.x - mu) * rs * s_w[c + 0] + s_b[c + 0];
    r.y = a.y + e1 + (p.y - mu) * rs * s_w[c + 1] + s_b[c + 1];
    r.z = a.z + e2 + (p.z - mu) * rs * s_w[c + 2] + s_b[c + 2];
    r.w = a.w + e3 + (p.w - mu) * rs * s_w[c + 3] + s_b[c + 3];

    ((float4*)(out + base))[lane] = r;
}

// ---------------------------------------------------------------------------
// Launch
// inputs: 0:m 1:z 2:m_prev 3:z_prev 4:x_prev 5:ln_m_w 6:ln_m_b
//         7:ln_z_w 8:ln_z_b 9:lin_w 10:lin_b
// output: [m (S*N*C_M floats) | z (N*N*C_Z floats)]
// ---------------------------------------------------------------------------
extern "C" void kernel_launch(void* const* d_in, const int* in_sizes, int n_in,
                              void* d_out, int out_size) {
    const float* m      = (const float*)d_in[0];
    const float* z      = (const float*)d_in[1];
    const float* m_prev = (const float*)d_in[2];
    const float* z_prev = (const float*)d_in[3];
    const float* x_prev = (const float*)d_in[4];
    const float* ln_m_w = (const float*)d_in[5];
    const float* ln_m_b = (const float*)d_in[6];
    const float* ln_z_w = (const float*)d_in[7];
    const float* ln_z_b = (const float*)d_in[8];
    const float* lin_w  = (const float*)d_in[9];
    const float* lin_b  = (const float*)d_in[10];

    float* out_m = (float*)d_out;
    const size_t m_elems = (size_t)S_DIM * NDIM * C_M;   // 25,165,824
    float* out_z = out_m + m_elems;

    // 1) copy m
    int n4 = (int)(m_elems / 4);                         // 6,291,456
    copy_m_kernel<<<(n4 + 255) / 256, 256>>>((const float4*)m, (float4*)out_m, n4);

    // 2) m[0] slice: + LayerNorm(m_prev[0])
    m0_kernel<<<(NDIM + 7) / 8, 256>>>(m, m_prev, ln_m_w, ln_m_b, out_m);

    // 3) z path
    long zrows = (long)NDIM * NDIM;                      // 589,824
    z_kernel<<<(int)((zrows + 7) / 8), 256>>>(z, z_prev, x_prev,
                                              ln_z_w, ln_z_b, lin_w, lin_b, out_z);
}

// round 4
// speedup vs baseline: 1.1376x; 1.1376x over previous
#include <cuda_runtime.h>

#define C_M 256
#define C_Z 128
#define NDIM 768
#define S_DIM 128
#define BIN_COUNT 15
#define BIN_START 3.25f
#define BIN_STEP 1.25f
#define LN_EPS 1e-5f

// ---------------------------------------------------------------------------
// Kernel 1: bulk copy of m -> out_m, 4 independent float4 per thread.
// n4 = 6,291,456 = 6144 blocks * 256 threads * 4 — exact, no guards.
// ---------------------------------------------------------------------------
__global__ __launch_bounds__(256) void copy_m_kernel(
    const float4* __restrict__ src, float4* __restrict__ dst) {
    int base = blockIdx.x * (256 * 4) + threadIdx.x;
    float4 a = __ldcs(src + base);
    float4 b = __ldcs(src + base + 256);
    float4 c = __ldcs(src + base + 512);
    float4 d = __ldcs(src + base + 768);
    __stcs(dst + base,       a);
    __stcs(dst + base + 256, b);
    __stcs(dst + base + 512, c);
    __stcs(dst + base + 768, d);
}

// ---------------------------------------------------------------------------
// Kernel 2: out_m[0,j,:] = m[0,j,:] + LayerNorm(m_prev[0,j,:])
// one warp per row, 256 channels -> 2 float4 per lane (tiny: 768 rows)
// ---------------------------------------------------------------------------
__global__ __launch_bounds__(256) void m0_kernel(
    const float* __restrict__ m, const float* __restrict__ m_prev,
    const float* __restrict__ w, const float* __restrict__ b,
    float* __restrict__ out) {
    int gwarp = (blockIdx.x * blockDim.x + threadIdx.x) >> 5;
    int lane = threadIdx.x & 31;
    if (gwarp >= NDIM) return;

    const float4* mp4 = (const float4*)(m_prev + (size_t)gwarp * C_M);
    float4 v0 = mp4[lane * 2];
    float4 v1 = mp4[lane * 2 + 1];

    float s  = v0.x + v0.y + v0.z + v0.w + v1.x + v1.y + v1.z + v1.w;
    float ss = v0.x*v0.x + v0.y*v0.y + v0.z*v0.z + v0.w*v0.w
             + v1.x*v1.x + v1.y*v1.y + v1.z*v1.z + v1.w*v1.w;
    #pragma unroll
    for (int o = 16; o > 0; o >>= 1) {
        s  += __shfl_xor_sync(0xFFFFFFFFu, s,  o);
        ss += __shfl_xor_sync(0xFFFFFFFFu, ss, o);
    }
    const float inv = 1.0f / C_M;
    float mu = s * inv;
    float var = ss * inv - mu * mu;
    float rs = rsqrtf(var + LN_EPS);

    const float4* mm4 = (const float4*)(m + (size_t)gwarp * C_M);
    const float4* w4 = (const float4*)w;
    const float4* b4 = (const float4*)b;
    float4* o4 = (float4*)(out + (size_t)gwarp * C_M);

    #pragma unroll
    for (int h = 0; h < 2; h++) {
        float4 a = mm4[lane * 2 + h];
        float4 v = (h == 0) ? v0 : v1;
        float4 wv = w4[lane * 2 + h];
        float4 bv = b4[lane * 2 + h];
        float4 r;
        r.x = a.x + (v.x - mu) * rs * wv.x + bv.x;
        r.y = a.y + (v.y - mu) * rs * wv.y + bv.y;
        r.z = a.z + (v.z - mu) * rs * wv.z + bv.z;
        r.w = a.w + (v.w - mu) * rs * wv.w + bv.w;
        o4[lane * 2 + h] = r;
    }
}

// ---------------------------------------------------------------------------
// Kernel 3: out_z[i,j,:] = z[i,j,:] + emb(i,j) + LayerNorm(z_prev[i,j,:])
// TWO rows per warp: 4 independent LDG.128 in flight, interleaved reductions.
// 589,824 rows = 36,864 blocks * 8 warps * 2 rows — exact, no guards.
// ---------------------------------------------------------------------------
__global__ __launch_bounds__(256) void z_kernel(
    const float* __restrict__ z, const float* __restrict__ z_prev,
    const float* __restrict__ x_prev,
    const float* __restrict__ ln_w, const float* __restrict__ ln_b,
    const float* __restrict__ lin_w, const float* __restrict__ lin_b,
    float* __restrict__ out) {
    __shared__ float s_lwT[BIN_COUNT * C_Z];   // lin_w transposed [bin][chan]
    __shared__ float s_lb[C_Z];
    __shared__ float s_w[C_Z];
    __shared__ float s_b[C_Z];

    int tid = threadIdx.x;
    for (int k = tid; k < BIN_COUNT * C_Z; k += 256) {
        int bb = k / C_Z;
        int cc = k - bb * C_Z;
        s_lwT[k] = lin_w[cc * BIN_COUNT + bb];
    }
    if (tid < C_Z) {
        s_lb[tid] = lin_b[tid];
        s_w[tid]  = ln_w[tid];
        s_b[tid]  = ln_b[tid];
    }
    __syncthreads();

    int warp = tid >> 5;
    int lane = tid & 31;
    long row0 = ((long)blockIdx.x * 8 + warp) * 2;
    long row1 = row0 + 1;

    size_t base0 = (size_t)row0 * C_Z;
    size_t base1 = base0 + C_Z;

    // issue all 4 independent 16B loads up front
    float4 p0 = __ldcs((const float4*)(z_prev + base0) + lane);
    float4 p1 = __ldcs((const float4*)(z_prev + base1) + lane);
    float4 a0 = __ldcs((const float4*)(z + base0) + lane);
    float4 a1 = __ldcs((const float4*)(z + base1) + lane);

    // distances + bins for both rows (x_prev is tiny; L1-broadcast)
    int i0 = (int)(row0 / NDIM), j0 = (int)(row0 - (long)i0 * NDIM);
    int i1 = i0, j1 = j0 + 1;          // row1 = row0+1, j0 is even so j1 < NDIM
    float dx0 = x_prev[i0 * 3 + 0] - x_prev[j0 * 3 + 0];
    float dy0 = x_prev[i0 * 3 + 1] - x_prev[j0 * 3 + 1];
    float dz0 = x_prev[i0 * 3 + 2] - x_prev[j0 * 3 + 2];
    float dx1 = x_prev[i1 * 3 + 0] - x_prev[j1 * 3 + 0];
    float dy1 = x_prev[i1 * 3 + 1] - x_prev[j1 * 3 + 1];
    float dz1 = x_prev[i1 * 3 + 2] - x_prev[j1 * 3 + 2];
    float d0 = sqrtf(dx0 * dx0 + dy0 * dy0 + dz0 * dz0);
    float d1 = sqrtf(dx1 * dx1 + dy1 * dy1 + dz1 * dz1);

    int bin0 = -1, bin1 = -1;
    #pragma unroll
    for (int k = 0; k < BIN_COUNT; k++) {
        float lo = BIN_START + k * BIN_STEP;
        float hi = (k < BIN_COUNT - 1) ? (lo + BIN_STEP) : 1e8f;
        if (d0 > lo && d0 < hi) bin0 = k;
        if (d1 > lo && d1 < hi) bin1 = k;
    }

    // interleaved warp reductions for both rows
    float s0  = p0.x + p0.y + p0.z + p0.w;
    float ss0 = p0.x*p0.x + p0.y*p0.y + p0.z*p0.z + p0.w*p0.w;
    float s1  = p1.x + p1.y + p1.z + p1.w;
    float ss1 = p1.x*p1.x + p1.y*p1.y + p1.z*p1.z + p1.w*p1.w;
    #pragma unroll
    for (int o = 16; o > 0; o >>= 1) {
        s0  += __shfl_xor_sync(0xFFFFFFFFu, s0,  o);
        s1  += __shfl_xor_sync(0xFFFFFFFFu, s1,  o);
        ss0 += __shfl_xor_sync(0xFFFFFFFFu, ss0, o);
        ss1 += __shfl_xor_sync(0xFFFFFFFFu, ss1, o);
    }
    const float inv = 1.0f / C_Z;
    float mu0 = s0 * inv, mu1 = s1 * inv;
    float rs0 = rsqrtf(ss0 * inv - mu0 * mu0 + LN_EPS);
    float rs1 = rsqrtf(ss1 * inv - mu1 * mu1 + LN_EPS);

    int c = lane * 4;
    float w0 = s_w[c + 0], w1 = s_w[c + 1], w2 = s_w[c + 2], w3 = s_w[c + 3];
    float bb0 = s_b[c + 0], bb1 = s_b[c + 1], bb2 = s_b[c + 2], bb3 = s_b[c + 3];
    float lb0 = s_lb[c + 0], lb1 = s_lb[c + 1], lb2 = s_lb[c + 2], lb3 = s_lb[c + 3];

    float e00 = lb0, e01 = lb1, e02 = lb2, e03 = lb3;
    if (bin0 >= 0) {
        const float* lw = s_lwT + bin0 * C_Z + c;
        e00 += lw[0]; e01 += lw[1]; e02 += lw[2]; e03 += lw[3];
    }
    float e10 = lb0, e11 = lb1, e12 = lb2, e13 = lb3;
    if (bin1 >= 0) {
        const float* lw = s_lwT + bin1 * C_Z + c;
        e10 += lw[0]; e11 += lw[1]; e12 += lw[2]; e13 += lw[3];
    }

    float4 r0, r1;
    r0.x = a0.x + e00 + (p0.x - mu0) * rs0 * w0 + bb0;
    r0.y = a0.y + e01 + (p0.y - mu0) * rs0 * w1 + bb1;
    r0.z = a0.z + e02 + (p0.z - mu0) * rs0 * w2 + bb2;
    r0.w = a0.w + e03 + (p0.w - mu0) * rs0 * w3 + bb3;
    r1.x = a1.x + e10 + (p1.x - mu1) * rs1 * w0 + bb0;
    r1.y = a1.y + e11 + (p1.y - mu1) * rs1 * w1 + bb1;
    r1.z = a1.z + e12 + (p1.z - mu1) * rs1 * w2 + bb2;
    r1.w = a1.w + e13 + (p1.w - mu1) * rs1 * w3 + bb3;

    __stcs((float4*)(out + base0) + lane, r0);
    __stcs((float4*)(out + base1) + lane, r1);
}

// ---------------------------------------------------------------------------
// Launch
// inputs: 0:m 1:z 2:m_prev 3:z_prev 4:x_prev 5:ln_m_w 6:ln_m_b
//         7:ln_z_w 8:ln_z_b 9:lin_w 10:lin_b
// output: [m (S*N*C_M floats) | z (N*N*C_Z floats)]
// ---------------------------------------------------------------------------
extern "C" void kernel_launch(void* const* d_in, const int* in_sizes, int n_in,
                              void* d_out, int out_size) {
    const float* m      = (const float*)d_in[0];
    const float* z      = (const float*)d_in[1];
    const float* m_prev = (const float*)d_in[2];
    const float* z_prev = (const float*)d_in[3];
    const float* x_prev = (const float*)d_in[4];
    const float* ln_m_w = (const float*)d_in[5];
    const float* ln_m_b = (const float*)d_in[6];
    const float* ln_z_w = (const float*)d_in[7];
    const float* ln_z_b = (const float*)d_in[8];
    const float* lin_w  = (const float*)d_in[9];
    const float* lin_b  = (const float*)d_in[10];

    float* out_m = (float*)d_out;
    const size_t m_elems = (size_t)S_DIM * NDIM * C_M;   // 25,165,824
    float* out_z = out_m + m_elems;

    // 1) z path (long pole) — 36,864 blocks * 16 rows = 589,824 rows exactly
    z_kernel<<<36864, 256>>>(z, z_prev, x_prev,
                             ln_z_w, ln_z_b, lin_w, lin_b, out_z);

    // 2) copy m: 6144 blocks * 1024 float4 = 6,291,456 float4 exactly
    copy_m_kernel<<<6144, 256>>>((const float4*)m, (float4*)out_m);

    // 3) m[0] slice: + LayerNorm(m_prev[0])
    m0_kernel<<<(NDIM + 7) / 8, 256>>>(m, m_prev, ln_m_w, ln_m_b, out_m);
}

// round 5
// speedup vs baseline: 1.2722x; 1.1183x over previous
#include <cuda_runtime.h>

#define C_M 256
#define C_Z 128
#define NDIM 768
#define S_DIM 128
#define BIN_COUNT 15
#define BIN_START 3.25f
#define BIN_STEP 1.25f
#define LN_EPS 1e-5f

// Block-range dispatch:
//   [0, 36864)            : z path, 8 warps/block, 2 rows/warp
//   [36864, 36864+6096)   : m copy, 1024 float4/block, starting at float4 49152
//   [42960, 42960+96)     : m[0] slice LN-add, 8 warps/block, 1 row/warp
#define ZBLOCKS   36864
#define CPBLOCKS  6096
#define M0BLOCKS  96
#define CP_OFFSET 49152   /* float4s in m[0] slice: 768*256/4 — handled by m0 path */

__global__ __launch_bounds__(256, 8) void fused_kernel(
    const float* __restrict__ m, const float* __restrict__ z,
    const float* __restrict__ m_prev, const float* __restrict__ z_prev,
    const float* __restrict__ x_prev,
    const float* __restrict__ ln_m_w, const float* __restrict__ ln_m_b,
    const float* __restrict__ ln_z_w, const float* __restrict__ ln_z_b,
    const float* __restrict__ lin_w, const float* __restrict__ lin_b,
    float* __restrict__ out_m, float* __restrict__ out_z) {

    int bid = blockIdx.x;
    int tid = threadIdx.x;

    if (bid < ZBLOCKS) {
        // ------------------------------------------------------------------
        // z path: out_z[row,:] = z + emb(bin) + LayerNorm(z_prev)
        // ------------------------------------------------------------------
        __shared__ float s_lwT[BIN_COUNT * C_Z];
        __shared__ float s_lb[C_Z];
        __shared__ float s_w[C_Z];
        __shared__ float s_b[C_Z];

        for (int k = tid; k < BIN_COUNT * C_Z; k += 256) {
            int bb = k / C_Z;
            int cc = k - bb * C_Z;
            s_lwT[k] = lin_w[cc * BIN_COUNT + bb];
        }
        if (tid < C_Z) {
            s_lb[tid] = lin_b[tid];
            s_w[tid]  = ln_z_w[tid];
            s_b[tid]  = ln_z_b[tid];
        }
        __syncthreads();

        int warp = tid >> 5;
        int lane = tid & 31;
        long row0 = ((long)bid * 8 + warp) * 2;

        size_t base0 = (size_t)row0 * C_Z;
        size_t base1 = base0 + C_Z;

        // 4 independent 16B loads up front
        float4 p0 = __ldcs((const float4*)(z_prev + base0) + lane);
        float4 p1 = __ldcs((const float4*)(z_prev + base1) + lane);
        float4 a0 = __ldcs((const float4*)(z + base0) + lane);
        float4 a1 = __ldcs((const float4*)(z + base1) + lane);

        int i0 = (int)(row0 / NDIM), j0 = (int)(row0 - (long)i0 * NDIM);
        float xi0 = x_prev[i0 * 3 + 0], xi1 = x_prev[i0 * 3 + 1], xi2 = x_prev[i0 * 3 + 2];
        float dx0 = xi0 - x_prev[j0 * 3 + 0];
        float dy0 = xi1 - x_prev[j0 * 3 + 1];
        float dz0 = xi2 - x_prev[j0 * 3 + 2];
        float dx1 = xi0 - x_prev[j0 * 3 + 3];
        float dy1 = xi1 - x_prev[j0 * 3 + 4];
        float dz1 = xi2 - x_prev[j0 * 3 + 5];
        float d0 = sqrtf(dx0 * dx0 + dy0 * dy0 + dz0 * dz0);
        float d1 = sqrtf(dx1 * dx1 + dy1 * dy1 + dz1 * dz1);

        // arithmetic binning, exact strict-bound semantics:
        //   k = floor((d-start)/step), clamp to 14; if d <= lower(k), k--.
        //   valid iff k>=0 and d > lower(k) (upper bound then holds by floor).
        int b0 = (int)floorf((d0 - BIN_START) * (1.0f / BIN_STEP));
        int b1 = (int)floorf((d1 - BIN_START) * (1.0f / BIN_STEP));
        b0 = min(b0, BIN_COUNT - 1);
        b1 = min(b1, BIN_COUNT - 1);
        if (b0 >= 0 && d0 <= BIN_START + b0 * BIN_STEP) b0--;
        if (b1 >= 0 && d1 <= BIN_START + b1 * BIN_STEP) b1--;
        if (b0 >= 0 && !(d0 > BIN_START + b0 * BIN_STEP)) b0 = -1;
        if (b1 >= 0 && !(d1 > BIN_START + b1 * BIN_STEP)) b1 = -1;

        float s0  = p0.x + p0.y + p0.z + p0.w;
        float ss0 = p0.x*p0.x + p0.y*p0.y + p0.z*p0.z + p0.w*p0.w;
        float s1  = p1.x + p1.y + p1.z + p1.w;
        float ss1 = p1.x*p1.x + p1.y*p1.y + p1.z*p1.z + p1.w*p1.w;
        #pragma unroll
        for (int o = 16; o > 0; o >>= 1) {
            s0  += __shfl_xor_sync(0xFFFFFFFFu, s0,  o);
            s1  += __shfl_xor_sync(0xFFFFFFFFu, s1,  o);
            ss0 += __shfl_xor_sync(0xFFFFFFFFu, ss0, o);
            ss1 += __shfl_xor_sync(0xFFFFFFFFu, ss1, o);
        }
        const float inv = 1.0f / C_Z;
        float mu0 = s0 * inv, mu1 = s1 * inv;
        float rs0 = rsqrtf(ss0 * inv - mu0 * mu0 + LN_EPS);
        float rs1 = rsqrtf(ss1 * inv - mu1 * mu1 + LN_EPS);

        int c = lane * 4;
        float w0 = s_w[c + 0], w1 = s_w[c + 1], w2 = s_w[c + 2], w3 = s_w[c + 3];
        float g0 = s_b[c + 0], g1 = s_b[c + 1], g2 = s_b[c + 2], g3 = s_b[c + 3];
        float lb0 = s_lb[c + 0], lb1 = s_lb[c + 1], lb2 = s_lb[c + 2], lb3 = s_lb[c + 3];

        float e00 = lb0, e01 = lb1, e02 = lb2, e03 = lb3;
        if (b0 >= 0) {
            const float* lw = s_lwT + b0 * C_Z + c;
            e00 += lw[0]; e01 += lw[1]; e02 += lw[2]; e03 += lw[3];
        }
        float e10 = lb0, e11 = lb1, e12 = lb2, e13 = lb3;
        if (b1 >= 0) {
            const float* lw = s_lwT + b1 * C_Z + c;
            e10 += lw[0]; e11 += lw[1]; e12 += lw[2]; e13 += lw[3];
        }

        float4 r0, r1;
        r0.x = a0.x + e00 + (p0.x - mu0) * rs0 * w0 + g0;
        r0.y = a0.y + e01 + (p0.y - mu0) * rs0 * w1 + g1;
        r0.z = a0.z + e02 + (p0.z - mu0) * rs0 * w2 + g2;
        r0.w = a0.w + e03 + (p0.w - mu0) * rs0 * w3 + g3;
        r1.x = a1.x + e10 + (p1.x - mu1) * rs1 * w0 + g0;
        r1.y = a1.y + e11 + (p1.y - mu1) * rs1 * w1 + g1;
        r1.z = a1.z + e12 + (p1.z - mu1) * rs1 * w2 + g2;
        r1.w = a1.w + e13 + (p1.w - mu1) * rs1 * w3 + g3;

        __stcs((float4*)(out_z + base0) + lane, r0);
        __stcs((float4*)(out_z + base1) + lane, r1);

    } else if (bid < ZBLOCKS + CPBLOCKS) {
        // ------------------------------------------------------------------
        // m copy (excluding m[0] slice): 4 independent float4 per thread
        // ------------------------------------------------------------------
        const float4* src = (const float4*)m;
        float4* dst = (float4*)out_m;
        int base = (bid - ZBLOCKS) * (256 * 4) + tid + CP_OFFSET;
        float4 a = __ldcs(src + base);
        float4 b = __ldcs(src + base + 256);
        float4 c = __ldcs(src + base + 512);
        float4 d = __ldcs(src + base + 768);
        __stcs(dst + base,       a);
        __stcs(dst + base + 256, b);
        __stcs(dst + base + 512, c);
        __stcs(dst + base + 768, d);

    } else {
        // ------------------------------------------------------------------
        // m[0] slice: out_m[0,j,:] = m[0,j,:] + LayerNorm(m_prev[0,j,:])
        // one warp per row, 2 float4 per lane
        // ------------------------------------------------------------------
        int gwarp = (bid - ZBLOCKS - CPBLOCKS) * 8 + (tid >> 5);
        int lane = tid & 31;

        const float4* mp4 = (const float4*)(m_prev + (size_t)gwarp * C_M);
        float4 v0 = mp4[lane * 2];
        float4 v1 = mp4[lane * 2 + 1];

        float s  = v0.x + v0.y + v0.z + v0.w + v1.x + v1.y + v1.z + v1.w;
        float ss = v0.x*v0.x + v0.y*v0.y + v0.z*v0.z + v0.w*v0.w
                 + v1.x*v1.x + v1.y*v1.y + v1.z*v1.z + v1.w*v1.w;
        #pragma unroll
        for (int o = 16; o > 0; o >>= 1) {
            s  += __shfl_xor_sync(0xFFFFFFFFu, s,  o);
            ss += __shfl_xor_sync(0xFFFFFFFFu, ss, o);
        }
        const float inv = 1.0f / C_M;
        float mu = s * inv;
        float rs = rsqrtf(ss * inv - mu * mu + LN_EPS);

        const float4* mm4 = (const float4*)(m + (size_t)gwarp * C_M);
        const float4* w4 = (const float4*)ln_m_w;
        const float4* b4 = (const float4*)ln_m_b;
        float4* o4 = (float4*)(out_m + (size_t)gwarp * C_M);

        #pragma unroll
        for (int h = 0; h < 2; h++) {
            float4 a = mm4[lane * 2 + h];
            float4 v = (h == 0) ? v0 : v1;
            float4 wv = w4[lane * 2 + h];
            float4 bv = b4[lane * 2 + h];
            float4 r;
            r.x = a.x + (v.x - mu) * rs * wv.x + bv.x;
            r.y = a.y + (v.y - mu) * rs * wv.y + bv.y;
            r.z = a.z + (v.z - mu) * rs * wv.z + bv.z;
            r.w = a.w + (v.w - mu) * rs * wv.w + bv.w;
            o4[lane * 2 + h] = r;
        }
    }
}

// ---------------------------------------------------------------------------
// Launch
// inputs: 0:m 1:z 2:m_prev 3:z_prev 4:x_prev 5:ln_m_w 6:ln_m_b
//         7:ln_z_w 8:ln_z_b 9:lin_w 10:lin_b
// output: [m (S*N*C_M floats) | z (N*N*C_Z floats)]
// ---------------------------------------------------------------------------
extern "C" void kernel_launch(void* const* d_in, const int* in_sizes, int n_in,
                              void* d_out, int out_size) {
    const float* m      = (const float*)d_in[0];
    const float* z      = (const float*)d_in[1];
    const float* m_prev = (const float*)d_in[2];
    const float* z_prev = (const float*)d_in[3];
    const float* x_prev = (const float*)d_in[4];
    const float* ln_m_w = (const float*)d_in[5];
    const float* ln_m_b = (const float*)d_in[6];
    const float* ln_z_w = (const float*)d_in[7];
    const float* ln_z_b = (const float*)d_in[8];
    const float* lin_w  = (const float*)d_in[9];
    const float* lin_b  = (const float*)d_in[10];

    float* out_m = (float*)d_out;
    const size_t m_elems = (size_t)S_DIM * NDIM * C_M;   // 25,165,824
    float* out_z = out_m + m_elems;

    fused_kernel<<<ZBLOCKS + CPBLOCKS + M0BLOCKS, 256>>>(
        m, z, m_prev, z_prev, x_prev,
        ln_m_w, ln_m_b, ln_z_w, ln_z_b, lin_w, lin_b,
        out_m, out_z);
}

// round 6
// speedup vs baseline: 1.2741x; 1.0015x over previous
#include <cuda_runtime.h>

#define C_M 256
#define C_Z 128
#define NDIM 768
#define S_DIM 128
#define BIN_COUNT 15
#define BIN_START 3.25f
#define BIN_STEP 1.25f
#define LN_EPS 1e-5f

// Block-range dispatch:
//   [0, 36864)            : z path, 8 warps/block, 2 rows/warp
//   [36864, 36864+6096)   : m copy, 1024 float4/block, starting at float4 49152
//   [42960, 42960+96)     : m[0] slice LN-add, 8 warps/block, 1 row/warp
#define ZBLOCKS   36864
#define CPBLOCKS  6096
#define M0BLOCKS  96
#define CP_OFFSET 49152   /* float4s in m[0] slice: 768*256/4 — handled by m0 path */

__global__ __launch_bounds__(256, 8) void fused_kernel(
    const float* __restrict__ m, const float* __restrict__ z,
    const float* __restrict__ m_prev, const float* __restrict__ z_prev,
    const float* __restrict__ x_prev,
    const float* __restrict__ ln_m_w, const float* __restrict__ ln_m_b,
    const float* __restrict__ ln_z_w, const float* __restrict__ ln_z_b,
    const float* __restrict__ lin_w, const float* __restrict__ lin_b,
    float* __restrict__ out_m, float* __restrict__ out_z) {

    int bid = blockIdx.x;
    int tid = threadIdx.x;

    if (bid < ZBLOCKS) {
        // ------------------------------------------------------------------
        // z path: out_z[row,:] = z + emb(bin) + LayerNorm(z_prev)
        // No smem, no barrier: params are tiny+hot -> L1 via __ldg.
        // ------------------------------------------------------------------
        int warp = tid >> 5;
        int lane = tid & 31;
        long row0 = ((long)bid * 8 + warp) * 2;

        size_t base0 = (size_t)row0 * C_Z;
        size_t base1 = base0 + C_Z;

        // 4 independent 16B streaming loads up front
        float4 p0 = __ldcs((const float4*)(z_prev + base0) + lane);
        float4 p1 = __ldcs((const float4*)(z_prev + base1) + lane);
        float4 a0 = __ldcs((const float4*)(z + base0) + lane);
        float4 a1 = __ldcs((const float4*)(z + base1) + lane);

        int i0 = (int)(row0 / NDIM), j0 = (int)(row0 - (long)i0 * NDIM);
        float xi0 = __ldg(x_prev + i0 * 3 + 0);
        float xi1 = __ldg(x_prev + i0 * 3 + 1);
        float xi2 = __ldg(x_prev + i0 * 3 + 2);
        float dx0 = xi0 - __ldg(x_prev + j0 * 3 + 0);
        float dy0 = xi1 - __ldg(x_prev + j0 * 3 + 1);
        float dz0 = xi2 - __ldg(x_prev + j0 * 3 + 2);
        float dx1 = xi0 - __ldg(x_prev + j0 * 3 + 3);
        float dy1 = xi1 - __ldg(x_prev + j0 * 3 + 4);
        float dz1 = xi2 - __ldg(x_prev + j0 * 3 + 5);
        float d0 = sqrtf(dx0 * dx0 + dy0 * dy0 + dz0 * dz0);
        float d1 = sqrtf(dx1 * dx1 + dy1 * dy1 + dz1 * dz1);

        // arithmetic binning, exact strict-bound semantics:
        //   k = floor((d-start)/step), clamp to 14; if d <= lower(k), k--.
        //   valid iff k>=0 and d > lower(k) (upper bound then holds by floor).
        int b0 = (int)floorf((d0 - BIN_START) * (1.0f / BIN_STEP));
        int b1 = (int)floorf((d1 - BIN_START) * (1.0f / BIN_STEP));
        b0 = min(b0, BIN_COUNT - 1);
        b1 = min(b1, BIN_COUNT - 1);
        if (b0 >= 0 && d0 <= BIN_START + b0 * BIN_STEP) b0--;
        if (b1 >= 0 && d1 <= BIN_START + b1 * BIN_STEP) b1--;
        if (b0 >= 0 && !(d0 > BIN_START + b0 * BIN_STEP)) b0 = -1;
        if (b1 >= 0 && !(d1 > BIN_START + b1 * BIN_STEP)) b1 = -1;

        // interleaved warp reductions for both rows
        float s0  = p0.x + p0.y + p0.z + p0.w;
        float ss0 = p0.x*p0.x + p0.y*p0.y + p0.z*p0.z + p0.w*p0.w;
        float s1  = p1.x + p1.y + p1.z + p1.w;
        float ss1 = p1.x*p1.x + p1.y*p1.y + p1.z*p1.z + p1.w*p1.w;
        #pragma unroll
        for (int o = 16; o > 0; o >>= 1) {
            s0  += __shfl_xor_sync(0xFFFFFFFFu, s0,  o);
            s1  += __shfl_xor_sync(0xFFFFFFFFu, s1,  o);
            ss0 += __shfl_xor_sync(0xFFFFFFFFu, ss0, o);
            ss1 += __shfl_xor_sync(0xFFFFFFFFu, ss1, o);
        }
        const float inv = 1.0f / C_Z;
        float mu0 = s0 * inv, mu1 = s1 * inv;
        float rs0 = rsqrtf(ss0 * inv - mu0 * mu0 + LN_EPS);
        float rs1 = rsqrtf(ss1 * inv - mu1 * mu1 + LN_EPS);

        int c = lane * 4;
        float4 wv = __ldg((const float4*)ln_z_w + lane);
        float4 gv = __ldg((const float4*)ln_z_b + lane);
        float4 lb = __ldg((const float4*)lin_b + lane);

        // bin-selected lin_w column: layout [C_Z][BIN_COUNT], L1-hot scalars
        float e00 = lb.x, e01 = lb.y, e02 = lb.z, e03 = lb.w;
        if (b0 >= 0) {
            e00 += __ldg(lin_w + (c + 0) * BIN_COUNT + b0);
            e01 += __ldg(lin_w + (c + 1) * BIN_COUNT + b0);
            e02 += __ldg(lin_w + (c + 2) * BIN_COUNT + b0);
            e03 += __ldg(lin_w + (c + 3) * BIN_COUNT + b0);
        }
        float e10 = lb.x, e11 = lb.y, e12 = lb.z, e13 = lb.w;
        if (b1 >= 0) {
            e10 += __ldg(lin_w + (c + 0) * BIN_COUNT + b1);
            e11 += __ldg(lin_w + (c + 1) * BIN_COUNT + b1);
            e12 += __ldg(lin_w + (c + 2) * BIN_COUNT + b1);
            e13 += __ldg(lin_w + (c + 3) * BIN_COUNT + b1);
        }

        float4 r0, r1;
        r0.x = a0.x + e00 + (p0.x - mu0) * rs0 * wv.x + gv.x;
        r0.y = a0.y + e01 + (p0.y - mu0) * rs0 * wv.y + gv.y;
        r0.z = a0.z + e02 + (p0.z - mu0) * rs0 * wv.z + gv.z;
        r0.w = a0.w + e03 + (p0.w - mu0) * rs0 * wv.w + gv.w;
        r1.x = a1.x + e10 + (p1.x - mu1) * rs1 * wv.x + gv.x;
        r1.y = a1.y + e11 + (p1.y - mu1) * rs1 * wv.y + gv.y;
        r1.z = a1.z + e12 + (p1.z - mu1) * rs1 * wv.z + gv.z;
        r1.w = a1.w + e13 + (p1.w - mu1) * rs1 * wv.w + gv.w;

        __stcs((float4*)(out_z + base0) + lane, r0);
        __stcs((float4*)(out_z + base1) + lane, r1);

    } else if (bid < ZBLOCKS + CPBLOCKS) {
        // ------------------------------------------------------------------
        // m copy (excluding m[0] slice): 4 independent float4 per thread
        // ------------------------------------------------------------------
        const float4* src = (const float4*)m;
        float4* dst = (float4*)out_m;
        int base = (bid - ZBLOCKS) * (256 * 4) + tid + CP_OFFSET;
        float4 a = __ldcs(src + base);
        float4 b = __ldcs(src + base + 256);
        float4 c = __ldcs(src + base + 512);
        float4 d = __ldcs(src + base + 768);
        __stcs(dst + base,       a);
        __stcs(dst + base + 256, b);
        __stcs(dst + base + 512, c);
        __stcs(dst + base + 768, d);

    } else {
        // ------------------------------------------------------------------
        // m[0] slice: out_m[0,j,:] = m[0,j,:] + LayerNorm(m_prev[0,j,:])
        // one warp per row, 2 float4 per lane
        // ------------------------------------------------------------------
        int gwarp = (bid - ZBLOCKS - CPBLOCKS) * 8 + (tid >> 5);
        int lane = tid & 31;

        const float4* mp4 = (const float4*)(m_prev + (size_t)gwarp * C_M);
        float4 v0 = mp4[lane * 2];
        float4 v1 = mp4[lane * 2 + 1];

        float s  = v0.x + v0.y + v0.z + v0.w + v1.x + v1.y + v1.z + v1.w;
        float ss = v0.x*v0.x + v0.y*v0.y + v0.z*v0.z + v0.w*v0.w
                 + v1.x*v1.x + v1.y*v1.y + v1.z*v1.z + v1.w*v1.w;
        #pragma unroll
        for (int o = 16; o > 0; o >>= 1) {
            s  += __shfl_xor_sync(0xFFFFFFFFu, s,  o);
            ss += __shfl_xor_sync(0xFFFFFFFFu, ss, o);
        }
        const float inv = 1.0f / C_M;
        float mu = s * inv;
        float rs = rsqrtf(ss * inv - mu * mu + LN_EPS);

        const float4* mm4 = (const float4*)(m + (size_t)gwarp * C_M);
        const float4* w4 = (const float4*)ln_m_w;
        const float4* b4 = (const float4*)ln_m_b;
        float4* o4 = (float4*)(out_m + (size_t)gwarp * C_M);

        #pragma unroll
        for (int h = 0; h < 2; h++) {
            float4 a = mm4[lane * 2 + h];
            float4 v = (h == 0) ? v0 : v1;
            float4 wv = w4[lane * 2 + h];
            float4 bv = b4[lane * 2 + h];
            float4 r;
            r.x = a.x + (v.x - mu) * rs * wv.x + bv.x;
            r.y = a.y + (v.y - mu) * rs * wv.y + bv.y;
            r.z = a.z + (v.z - mu) * rs * wv.z + bv.z;
            r.w = a.w + (v.w - mu) * rs * wv.w + bv.w;
            o4[lane * 2 + h] = r;
        }
    }
}

// ---------------------------------------------------------------------------
// Launch
// inputs: 0:m 1:z 2:m_prev 3:z_prev 4:x_prev 5:ln_m_w 6:ln_m_b
//         7:ln_z_w 8:ln_z_b 9:lin_w 10:lin_b
// output: [m (S*N*C_M floats) | z (N*N*C_Z floats)]
// ---------------------------------------------------------------------------
extern "C" void kernel_launch(void* const* d_in, const int* in_sizes, int n_in,
                              void* d_out, int out_size) {
    const float* m      = (const float*)d_in[0];
    const float* z      = (const float*)d_in[1];
    const float* m_prev = (const float*)d_in[2];
    const float* z_prev = (const float*)d_in[3];
    const float* x_prev = (const float*)d_in[4];
    const float* ln_m_w = (const float*)d_in[5];
    const float* ln_m_b = (const float*)d_in[6];
    const float* ln_z_w = (const float*)d_in[7];
    const float* ln_z_b = (const float*)d_in[8];
    const float* lin_w  = (const float*)d_in[9];
    const float* lin_b  = (const float*)d_in[10];

    float* out_m = (float*)d_out;
    const size_t m_elems = (size_t)S_DIM * NDIM * C_M;   // 25,165,824
    float* out_z = out_m + m_elems;

    fused_kernel<<<ZBLOCKS + CPBLOCKS + M0BLOCKS, 256>>>(
        m, z, m_prev, z_prev, x_prev,
        ln_m_w, ln_m_b, ln_z_w, ln_z_b, lin_w, lin_b,
        out_m, out_z);
}

// round 7
// speedup vs baseline: 1.3418x; 1.0532x over previous
#include <cuda_runtime.h>

#define C_M 256
#define C_Z 128
#define NDIM 768
#define S_DIM 128
#define BIN_COUNT 15
#define BIN_START 3.25f
#define BIN_STEP 1.25f
#define LN_EPS 1e-5f

// Block-range dispatch:
//   [0, 36864)            : z path, 8 warps/block, 2 rows/warp
//   [36864, 36864+6096)   : m copy, 1024 float4/block, starting at float4 49152
//   [42960, 42960+96)     : m[0] slice LN-add, 8 warps/block, 1 row/warp
#define ZBLOCKS   36864
#define CPBLOCKS  6096
#define M0BLOCKS  96
#define CP_OFFSET 49152   /* float4s in m[0] slice: 768*256/4 — handled by m0 path */

// Transposed lin_w: g_lwT[bin*C_Z + c] = lin_w[c*BIN_COUNT + bin]
__device__ __align__(16) float g_lwT[BIN_COUNT * C_Z];

__global__ void prep_kernel(const float* __restrict__ lin_w) {
    int t = threadIdx.x;
    #pragma unroll
    for (int k = t; k < BIN_COUNT * C_Z; k += 256) {
        int b = k >> 7;          // k / C_Z
        int c = k & (C_Z - 1);   // k % C_Z
        g_lwT[k] = lin_w[c * BIN_COUNT + b];
    }
}

__global__ __launch_bounds__(256, 8) void fused_kernel(
    const float* __restrict__ m, const float* __restrict__ z,
    const float* __restrict__ m_prev, const float* __restrict__ z_prev,
    const float* __restrict__ x_prev,
    const float* __restrict__ ln_m_w, const float* __restrict__ ln_m_b,
    const float* __restrict__ ln_z_w, const float* __restrict__ ln_z_b,
    const float* __restrict__ lin_b,
    float* __restrict__ out_m, float* __restrict__ out_z) {

    int bid = blockIdx.x;
    int tid = threadIdx.x;

    if (bid < ZBLOCKS) {
        // ------------------------------------------------------------------
        // z path: out_z[row,:] = z + emb(bin) + LayerNorm(z_prev)
        // Params via L1 (__ldg); embedding column via coalesced float4 from
        // the pre-transposed g_lwT (bin is warp-uniform per row).
        // ------------------------------------------------------------------
        int warp = tid >> 5;
        int lane = tid & 31;
        long row0 = ((long)bid * 8 + warp) * 2;

        size_t base0 = (size_t)row0 * C_Z;
        size_t base1 = base0 + C_Z;

        // 4 independent 16B streaming loads up front
        float4 p0 = __ldcs((const float4*)(z_prev + base0) + lane);
        float4 p1 = __ldcs((const float4*)(z_prev + base1) + lane);
        float4 a0 = __ldcs((const float4*)(z + base0) + lane);
        float4 a1 = __ldcs((const float4*)(z + base1) + lane);

        int i0 = (int)(row0 / NDIM), j0 = (int)(row0 - (long)i0 * NDIM);
        float xi0 = __ldg(x_prev + i0 * 3 + 0);
        float xi1 = __ldg(x_prev + i0 * 3 + 1);
        float xi2 = __ldg(x_prev + i0 * 3 + 2);
        float dx0 = xi0 - __ldg(x_prev + j0 * 3 + 0);
        float dy0 = xi1 - __ldg(x_prev + j0 * 3 + 1);
        float dz0 = xi2 - __ldg(x_prev + j0 * 3 + 2);
        float dx1 = xi0 - __ldg(x_prev + j0 * 3 + 3);
        float dy1 = xi1 - __ldg(x_prev + j0 * 3 + 4);
        float dz1 = xi2 - __ldg(x_prev + j0 * 3 + 5);
        float d0 = sqrtf(dx0 * dx0 + dy0 * dy0 + dz0 * dz0);
        float d1 = sqrtf(dx1 * dx1 + dy1 * dy1 + dz1 * dz1);

        // arithmetic binning, exact strict-bound semantics:
        //   k = floor((d-start)/step), clamp to 14; if d <= lower(k), k--.
        //   valid iff k>=0 and d > lower(k) (upper bound then holds by floor).
        int b0 = (int)floorf((d0 - BIN_START) * (1.0f / BIN_STEP));
        int b1 = (int)floorf((d1 - BIN_START) * (1.0f / BIN_STEP));
        b0 = min(b0, BIN_COUNT - 1);
        b1 = min(b1, BIN_COUNT - 1);
        if (b0 >= 0 && d0 <= BIN_START + b0 * BIN_STEP) b0--;
        if (b1 >= 0 && d1 <= BIN_START + b1 * BIN_STEP) b1--;
        if (b0 >= 0 && !(d0 > BIN_START + b0 * BIN_STEP)) b0 = -1;
        if (b1 >= 0 && !(d1 > BIN_START + b1 * BIN_STEP)) b1 = -1;

        // embedding columns: one coalesced float4 per row (L1-hot, 7.5 KB table)
        float4 lb = __ldg((const float4*)lin_b + lane);
        float4 e0 = lb, e1 = lb;
        if (b0 >= 0) {
            float4 t = __ldg((const float4*)(g_lwT + b0 * C_Z) + lane);
            e0.x += t.x; e0.y += t.y; e0.z += t.z; e0.w += t.w;
        }
        if (b1 >= 0) {
            float4 t = __ldg((const float4*)(g_lwT + b1 * C_Z) + lane);
            e1.x += t.x; e1.y += t.y; e1.z += t.z; e1.w += t.w;
        }

        // interleaved warp reductions for both rows
        float s0  = p0.x + p0.y + p0.z + p0.w;
        float ss0 = p0.x*p0.x + p0.y*p0.y + p0.z*p0.z + p0.w*p0.w;
        float s1  = p1.x + p1.y + p1.z + p1.w;
        float ss1 = p1.x*p1.x + p1.y*p1.y + p1.z*p1.z + p1.w*p1.w;
        #pragma unroll
        for (int o = 16; o > 0; o >>= 1) {
            s0  += __shfl_xor_sync(0xFFFFFFFFu, s0,  o);
            s1  += __shfl_xor_sync(0xFFFFFFFFu, s1,  o);
            ss0 += __shfl_xor_sync(0xFFFFFFFFu, ss0, o);
            ss1 += __shfl_xor_sync(0xFFFFFFFFu, ss1, o);
        }
        const float inv = 1.0f / C_Z;
        float mu0 = s0 * inv, mu1 = s1 * inv;
        float rs0 = rsqrtf(ss0 * inv - mu0 * mu0 + LN_EPS);
        float rs1 = rsqrtf(ss1 * inv - mu1 * mu1 + LN_EPS);

        float4 wv = __ldg((const float4*)ln_z_w + lane);
        float4 gv = __ldg((const float4*)ln_z_b + lane);

        float4 r0, r1;
        r0.x = a0.x + e0.x + (p0.x - mu0) * rs0 * wv.x + gv.x;
        r0.y = a0.y + e0.y + (p0.y - mu0) * rs0 * wv.y + gv.y;
        r0.z = a0.z + e0.z + (p0.z - mu0) * rs0 * wv.z + gv.z;
        r0.w = a0.w + e0.w + (p0.w - mu0) * rs0 * wv.w + gv.w;
        r1.x = a1.x + e1.x + (p1.x - mu1) * rs1 * wv.x + gv.x;
        r1.y = a1.y + e1.y + (p1.y - mu1) * rs1 * wv.y + gv.y;
        r1.z = a1.z + e1.z + (p1.z - mu1) * rs1 * wv.z + gv.z;
        r1.w = a1.w + e1.w + (p1.w - mu1) * rs1 * wv.w + gv.w;

        __stcs((float4*)(out_z + base0) + lane, r0);
        __stcs((float4*)(out_z + base1) + lane, r1);

    } else if (bid < ZBLOCKS + CPBLOCKS) {
        // ------------------------------------------------------------------
        // m copy (excluding m[0] slice): 4 independent float4 per thread
        // ------------------------------------------------------------------
        const float4* src = (const float4*)m;
        float4* dst = (float4*)out_m;
        int base = (bid - ZBLOCKS) * (256 * 4) + tid + CP_OFFSET;
        float4 a = __ldcs(src + base);
        float4 b = __ldcs(src + base + 256);
        float4 c = __ldcs(src + base + 512);
        float4 d = __ldcs(src + base + 768);
        __stcs(dst + base,       a);
        __stcs(dst + base + 256, b);
        __stcs(dst + base + 512, c);
        __stcs(dst + base + 768, d);

    } else {
        // ------------------------------------------------------------------
        // m[0] slice: out_m[0,j,:] = m[0,j,:] + LayerNorm(m_prev[0,j,:])
        // one warp per row, 2 float4 per lane
        // ------------------------------------------------------------------
        int gwarp = (bid - ZBLOCKS - CPBLOCKS) * 8 + (tid >> 5);
        int lane = tid & 31;

        const float4* mp4 = (const float4*)(m_prev + (size_t)gwarp * C_M);
        float4 v0 = mp4[lane * 2];
        float4 v1 = mp4[lane * 2 + 1];

        float s  = v0.x + v0.y + v0.z + v0.w + v1.x + v1.y + v1.z + v1.w;
        float ss = v0.x*v0.x + v0.y*v0.y + v0.z*v0.z + v0.w*v0.w
                 + v1.x*v1.x + v1.y*v1.y + v1.z*v1.z + v1.w*v1.w;
        #pragma unroll
        for (int o = 16; o > 0; o >>= 1) {
            s  += __shfl_xor_sync(0xFFFFFFFFu, s,  o);
            ss += __shfl_xor_sync(0xFFFFFFFFu, ss, o);
        }
        const float inv = 1.0f / C_M;
        float mu = s * inv;
        float rs = rsqrtf(ss * inv - mu * mu + LN_EPS);

        const float4* mm4 = (const float4*)(m + (size_t)gwarp * C_M);
        const float4* w4 = (const float4*)ln_m_w;
        const float4* b4 = (const float4*)ln_m_b;
        float4* o4 = (float4*)(out_m + (size_t)gwarp * C_M);

        #pragma unroll
        for (int h = 0; h < 2; h++) {
            float4 a = mm4[lane * 2 + h];
            float4 v = (h == 0) ? v0 : v1;
            float4 wv = w4[lane * 2 + h];
            float4 bv = b4[lane * 2 + h];
            float4 r;
            r.x = a.x + (v.x - mu) * rs * wv.x + bv.x;
            r.y = a.y + (v.y - mu) * rs * wv.y + bv.y;
            r.z = a.z + (v.z - mu) * rs * wv.z + bv.z;
            r.w = a.w + (v.w - mu) * rs * wv.w + bv.w;
            o4[lane * 2 + h] = r;
        }
    }
}

// ---------------------------------------------------------------------------
// Launch
// inputs: 0:m 1:z 2:m_prev 3:z_prev 4:x_prev 5:ln_m_w 6:ln_m_b
//         7:ln_z_w 8:ln_z_b 9:lin_w 10:lin_b
// output: [m (S*N*C_M floats) | z (N*N*C_Z floats)]
// ---------------------------------------------------------------------------
extern "C" void kernel_launch(void* const* d_in, const int* in_sizes, int n_in,
                              void* d_out, int out_size) {
    const float* m      = (const float*)d_in[0];
    const float* z      = (const float*)d_in[1];
    const float* m_prev = (const float*)d_in[2];
    const float* z_prev = (const float*)d_in[3];
    const float* x_prev = (const float*)d_in[4];
    const float* ln_m_w = (const float*)d_in[5];
    const float* ln_m_b = (const float*)d_in[6];
    const float* ln_z_w = (const float*)d_in[7];
    const float* ln_z_b = (const float*)d_in[8];
    const float* lin_w  = (const float*)d_in[9];
    const float* lin_b  = (const float*)d_in[10];

    float* out_m = (float*)d_out;
    const size_t m_elems = (size_t)S_DIM * NDIM * C_M;   // 25,165,824
    float* out_z = out_m + m_elems;

    // 1) one-time transpose of lin_w into __device__ scratch (same stream -> ordered)
    prep_kernel<<<1, 256>>>(lin_w);

    // 2) fused bulk pass
    fused_kernel<<<ZBLOCKS + CPBLOCKS + M0BLOCKS, 256>>>(
        m, z, m_prev, z_prev, x_prev,
        ln_m_w, ln_m_b, ln_z_w, ln_z_b, lin_b,
        out_m, out_z);
}